// round 14
// baseline (speedup 1.0000x reference)
#include <cuda_runtime.h>
#include <cuda_fp16.h>
#include <math.h>
#include <stdint.h>

// Problem constants
#define BB    2
#define NN    2048
#define DIM   256
#define HH    8
#define HD    32
#define HD2   64
#define ROWS  (BB*NN)          // 4096
#define SCALE 0.17677669529663689f  // 32^-0.5
#define LOG2E 1.4426950408889634f
#define LAMBDA_INIT 0.1f
#define EPS   1e-5f

// ---------------- half weight/activation pool (static, no allocation) ------
#define OC_OFF   0u
#define WQ_OFF   1048576u
#define WK_OFF   1179648u      // Wk (512x256) then Wv (256x256) contiguous
#define WV_OFF   1310720u
#define WO_OFF   1376256u
#define F1_OFF   1441792u
#define F2_OFF   1703936u
#define HW_TOTAL 1966080u
__device__ __half g_hw [HW_TOTAL];     // ocean + all weights (fp16)
__device__ __half g_hx [ROWS*DIM];     // LN1 out
__device__ __half g_hQ [ROWS*2*DIM];   // Q (pre-scaled by SCALE*LOG2E)
__device__ __half g_hKV[ROWS*768];     // fused K(512) | V(256) per row
__device__ __half g_hatt[ROWS*DIM];
__device__ __half g_hy [ROWS*DIM];     // LN2 out
__device__ __half g_hh [ROWS*4*DIM];   // MLP hidden

// ---------------- helpers ---------------------------------------------------
__device__ __forceinline__ void mma_f16(float* d, const uint32_t* a,
                                        uint32_t b0, uint32_t b1) {
    asm volatile("mma.sync.aligned.m16n8k16.row.col.f32.f16.f16.f32 "
                 "{%0,%1,%2,%3},{%4,%5,%6,%7},{%8,%9},{%0,%1,%2,%3};"
                 : "+f"(d[0]), "+f"(d[1]), "+f"(d[2]), "+f"(d[3])
                 : "r"(a[0]), "r"(a[1]), "r"(a[2]), "r"(a[3]),
                   "r"(b0), "r"(b1));
}
__device__ __forceinline__ void ldsm4(uint32_t* r, uint32_t addr) {
    asm volatile("ldmatrix.sync.aligned.m8n8.x4.shared.b16 {%0,%1,%2,%3}, [%4];"
                 : "=r"(r[0]), "=r"(r[1]), "=r"(r[2]), "=r"(r[3]) : "r"(addr));
}
__device__ __forceinline__ uint32_t packh2(float x, float y) {
    __half2 h = __floats2half2_rn(x, y);
    return *reinterpret_cast<uint32_t*>(&h);
}
__device__ __forceinline__ float ex2f(float x) {
    float y;
    asm("ex2.approx.f32 %0, %1;" : "=f"(y) : "f"(x));
    return y;
}
__device__ __forceinline__ void cp16(uint32_t saddr, const void* g) {
    asm volatile("cp.async.cg.shared.global [%0], [%1], 16;\n" :: "r"(saddr), "l"(g));
}
__device__ __forceinline__ void cp_commit() { asm volatile("cp.async.commit_group;\n"); }
template<int N> __device__ __forceinline__ void cp_wait() {
    asm volatile("cp.async.wait_group %0;\n" :: "n"(N));
}

// ---------------- fused LN1 + fp32->fp16 conversion -------------------------
__global__ void __launch_bounds__(256) ln_cvt_kernel(
    const float* __restrict__ drift, __half* __restrict__ hx,
    const float* __restrict__ gamma, const float* __restrict__ beta,
    const float* __restrict__ oc,
    const float* __restrict__ wq, const float* __restrict__ wk,
    const float* __restrict__ wv, const float* __restrict__ wo,
    const float* __restrict__ f1, const float* __restrict__ f2,
    __half* __restrict__ dst, float* __restrict__ oout)
{
    if (blockIdx.x < 512) {
        int wid  = threadIdx.x >> 5;
        int lane = threadIdx.x & 31;
        int row  = blockIdx.x * 8 + wid;
        const float4* p = (const float4*)(drift + (size_t)row * DIM);
        float4 v0 = p[lane*2], v1 = p[lane*2+1];

        float s = v0.x+v0.y+v0.z+v0.w + v1.x+v1.y+v1.z+v1.w;
        #pragma unroll
        for (int o = 16; o; o >>= 1) s += __shfl_xor_sync(0xffffffffu, s, o);
        float mu = s * (1.0f/DIM);

        float d0x=v0.x-mu,d0y=v0.y-mu,d0z=v0.z-mu,d0w=v0.w-mu;
        float d1x=v1.x-mu,d1y=v1.y-mu,d1z=v1.z-mu,d1w=v1.w-mu;
        float q = d0x*d0x+d0y*d0y+d0z*d0z+d0w*d0w + d1x*d1x+d1y*d1y+d1z*d1z+d1w*d1w;
        #pragma unroll
        for (int o = 16; o; o >>= 1) q += __shfl_xor_sync(0xffffffffu, q, o);
        float rstd = rsqrtf(q * (1.0f/DIM) + EPS);

        const float4* gp = (const float4*)gamma;
        const float4* bp = (const float4*)beta;
        float4 g0 = gp[lane*2], g1 = gp[lane*2+1];
        float4 b0 = bp[lane*2], b1 = bp[lane*2+1];

        uint4 u;
        u.x = packh2(d0x*rstd*g0.x + b0.x, d0y*rstd*g0.y + b0.y);
        u.y = packh2(d0z*rstd*g0.z + b0.z, d0w*rstd*g0.w + b0.w);
        u.z = packh2(d1x*rstd*g1.x + b1.x, d1y*rstd*g1.y + b1.y);
        u.w = packh2(d1z*rstd*g1.z + b1.z, d1w*rstd*g1.w + b1.w);
        *(uint4*)&hx[(size_t)row*DIM + lane*8] = u;
    } else {
        uint32_t fi = ((uint32_t)(blockIdx.x - 512)*256u + threadIdx.x)*4u;
        if (fi >= HW_TOTAL) return;
        const float* src; uint32_t base;
        if      (fi < WQ_OFF) { src = oc; base = OC_OFF; }
        else if (fi < WK_OFF) { src = wq; base = WQ_OFF; }
        else if (fi < WV_OFF) { src = wk; base = WK_OFF; }
        else if (fi < WO_OFF) { src = wv; base = WV_OFF; }
        else if (fi < F1_OFF) { src = wo; base = WO_OFF; }
        else if (fi < F2_OFF) { src = f1; base = F1_OFF; }
        else                  { src = f2; base = F2_OFF; }
        float4 v = *(const float4*)&src[fi - base];
        if (fi < WQ_OFF) *(float4*)&oout[fi] = v;   // ocean passthrough (fp32)
        uint2 u = make_uint2(packh2(v.x, v.y), packh2(v.z, v.w));
        *(uint2*)&dst[fi] = u;
    }
}

// ---------------- LayerNorm standalone (for ln2) ----------------------------
__global__ void __launch_bounds__(256) ln_half(const float* __restrict__ in,
                                               __half* __restrict__ out,
                                               const float* __restrict__ gamma,
                                               const float* __restrict__ beta)
{
    int wid  = threadIdx.x >> 5;
    int lane = threadIdx.x & 31;
    int row  = blockIdx.x * 8 + wid;
    const float4* p = (const float4*)(in + (size_t)row * DIM);
    float4 v0 = p[lane*2], v1 = p[lane*2+1];

    float s = v0.x+v0.y+v0.z+v0.w + v1.x+v1.y+v1.z+v1.w;
    #pragma unroll
    for (int o = 16; o; o >>= 1) s += __shfl_xor_sync(0xffffffffu, s, o);
    float mu = s * (1.0f/DIM);

    float d0x=v0.x-mu,d0y=v0.y-mu,d0z=v0.z-mu,d0w=v0.w-mu;
    float d1x=v1.x-mu,d1y=v1.y-mu,d1z=v1.z-mu,d1w=v1.w-mu;
    float q = d0x*d0x+d0y*d0y+d0z*d0z+d0w*d0w + d1x*d1x+d1y*d1y+d1z*d1z+d1w*d1w;
    #pragma unroll
    for (int o = 16; o; o >>= 1) q += __shfl_xor_sync(0xffffffffu, q, o);
    float rstd = rsqrtf(q * (1.0f/DIM) + EPS);

    const float4* gp = (const float4*)gamma;
    const float4* bp = (const float4*)beta;
    float4 g0 = gp[lane*2], g1 = gp[lane*2+1];
    float4 b0 = bp[lane*2], b1 = bp[lane*2+1];

    uint4 u;
    u.x = packh2(d0x*rstd*g0.x + b0.x, d0y*rstd*g0.y + b0.y);
    u.y = packh2(d0z*rstd*g0.z + b0.z, d0w*rstd*g0.w + b0.w);
    u.z = packh2(d1x*rstd*g1.x + b1.x, d1y*rstd*g1.y + b1.y);
    u.w = packh2(d1z*rstd*g1.z + b1.z, d1w*rstd*g1.w + b1.w);
    *(uint4*)&out[(size_t)row*DIM + lane*8] = u;
}

// ---------------- fp16 GEMM core: cp.async 3-stage, ldmatrix ----------------
// C[M,N] = A[M,K] * B[N,K]^T. Tile BMxBN, K-chunk 32 halves, 256 threads.
// BM=128: warps 4(M)x2(N); BM=64: warps 2(M)x4(N).
// EPI: 0 = *oscale -> half, 1 = +res -> float, 2 = gelu(.+bias) -> half,
//      3 = +bias+res -> float
#define GSTR 20
#define NSTAGE 3
#define GEMM_SMEM(BM,BN) ((NSTAGE*((BM)+(BN))*GSTR)*4)
template<int EPI, int BM, int BN>
__device__ __forceinline__ void gemm_core(const __half* __restrict__ A,
                                          const __half* __restrict__ Bm,
                                          const float* __restrict__ bias,
                                          const float* __restrict__ res,
                                          void* __restrict__ Cout,
                                          int N, int K, float oscale,
                                          int m0, int n0)
{
    constexpr int WNN = (BM == 128) ? 2 : 4;   // warps along N
    constexpr int WNW = BN / WNN;              // warp N width
    constexpr int NI  = WNW / 8;
    constexpr int NJ  = WNW / 16;
    constexpr int GSM_A = NSTAGE*BM*GSTR;

    extern __shared__ uint32_t smu[];
    uint32_t* sA = smu;
    uint32_t* sB = smu + GSM_A;
    const uint32_t sA_base = (uint32_t)__cvta_generic_to_shared(sA);
    const uint32_t sB_base = (uint32_t)__cvta_generic_to_shared(sB);

    const int tid  = threadIdx.x;
    const int lane = tid & 31;
    const int warp = tid >> 5;
    const int gr   = lane >> 2;
    const int gc   = lane & 3;
    const int wm   = warp / WNN;
    const int wn   = warp % WNN;

    const int lrow = tid >> 2, lseg = tid & 3;

    const int la = lane & 15,                 sa = lane >> 4;
    const int lb = (lane & 7) + ((lane >> 4) << 3), sb = (lane >> 3) & 1;

    float c[2][NI][4];
    #pragma unroll
    for (int mi=0; mi<2; mi++)
        #pragma unroll
        for (int ni=0; ni<NI; ni++)
            #pragma unroll
            for (int i=0; i<4; i++) c[mi][ni][i] = 0.f;

    auto fill = [&](int stage, int k0) {
        cp16(sA_base + (((stage*BM + lrow)*GSTR + lseg*4) << 2),
             A + (size_t)(m0 + lrow)*K + k0 + lseg*8);
        if (BM == 128)
            cp16(sA_base + (((stage*BM + lrow + 64)*GSTR + lseg*4) << 2),
                 A + (size_t)(m0 + lrow + 64)*K + k0 + lseg*8);
        cp16(sB_base + (((stage*BN + lrow)*GSTR + lseg*4) << 2),
             Bm + (size_t)(n0 + lrow)*K + k0 + lseg*8);
        if (BN == 128)
            cp16(sB_base + (((stage*BN + lrow + 64)*GSTR + lseg*4) << 2),
                 Bm + (size_t)(n0 + lrow + 64)*K + k0 + lseg*8);
    };

    auto compute = [&](int stage) {
        const uint32_t aBase = sA_base + (((stage*BM + wm*32)*GSTR) << 2);
        const uint32_t bBase = sB_base + (((stage*BN + wn*WNW)*GSTR) << 2);
        #pragma unroll
        for (int kc = 0; kc < 2; kc++) {
            const int kb = kc*8;
            uint32_t af[2][4], bf[NJ][4];
            #pragma unroll
            for (int mi = 0; mi < 2; mi++)
                ldsm4(af[mi], aBase + (((mi*16 + la)*GSTR + kb + sa*4) << 2));
            #pragma unroll
            for (int nj = 0; nj < NJ; nj++)
                ldsm4(bf[nj], bBase + (((nj*16 + lb)*GSTR + kb + sb*4) << 2));
            #pragma unroll
            for (int mi = 0; mi < 2; mi++)
                #pragma unroll
                for (int ni = 0; ni < NI; ni++)
                    mma_f16(c[mi][ni], af[mi],
                            bf[ni>>1][(ni&1)*2], bf[ni>>1][(ni&1)*2+1]);
        }
    };

    const int nIter = K >> 5;
    fill(0, 0);  cp_commit();
    fill(1, 32); cp_commit();
    for (int it = 0; it < nIter; it++) {
        cp_wait<1>();
        __syncthreads();
        if (it + 2 < nIter) fill((it+2) % 3, (it+2)*32);
        cp_commit();
        compute(it % 3);
    }

    #pragma unroll
    for (int ni = 0; ni < NI; ni++) {
        const int col = n0 + wn*WNW + ni*8 + 2*gc;
        float2 bi = make_float2(0.f, 0.f);
        if (EPI == 2 || EPI == 3) bi = *(const float2*)&bias[col];
        #pragma unroll
        for (int mi = 0; mi < 2; mi++) {
            const int row0 = m0 + wm*32 + mi*16 + gr;
            #pragma unroll
            for (int hh2 = 0; hh2 < 2; hh2++) {
                const int row = row0 + hh2*8;
                float2 v = make_float2(c[mi][ni][hh2*2], c[mi][ni][hh2*2+1]);
                if (EPI == 0) { v.x *= oscale; v.y *= oscale; }
                if (EPI == 2) {
                    v.x += bi.x; v.y += bi.y;
                    v.x = 0.5f*v.x*(1.0f + erff(v.x*0.7071067811865475f));
                    v.y = 0.5f*v.y*(1.0f + erff(v.y*0.7071067811865475f));
                }
                if (EPI == 3) { v.x += bi.x; v.y += bi.y; }
                if (EPI == 1 || EPI == 3) {
                    float2 r = *(const float2*)&res[(size_t)row*N + col];
                    v.x += r.x; v.y += r.y;
                }
                if (EPI == 0 || EPI == 2) {
                    ((uint32_t*)Cout)[((size_t)row*N + col) >> 1] = packh2(v.x, v.y);
                } else {
                    *(float2*)&((float*)Cout)[(size_t)row*N + col] = v;
                }
            }
        }
    }
}

template<int EPI, int BM, int BN>
__global__ void __launch_bounds__(256) gemm_h(const __half* __restrict__ A,
                                              const __half* __restrict__ Bm,
                                              const float* __restrict__ bias,
                                              const float* __restrict__ res,
                                              void* __restrict__ Cout,
                                              int N, int K, float oscale)
{
    gemm_core<EPI,BM,BN>(A, Bm, bias, res, Cout, N, K, oscale,
                         blockIdx.y*BM, blockIdx.x*BN);
}

// fused Q + KV projection: blocks x<8 -> Q (N=512), x>=8 -> KV (N=768)
__global__ void __launch_bounds__(256) gemm_qkv(const __half* __restrict__ x,
                                                const __half* __restrict__ wq,
                                                __half* __restrict__ Qout,
                                                const __half* __restrict__ oc,
                                                const __half* __restrict__ wkv,
                                                __half* __restrict__ KVout)
{
    if (blockIdx.x < 8)
        gemm_core<0,128,64>(x, wq, nullptr, nullptr, Qout, 512, 256, SCALE*LOG2E,
                            blockIdx.y*128, blockIdx.x*64);
    else
        gemm_core<0,128,64>(oc, wkv, nullptr, nullptr, KVout, 768, 256, 1.0f,
                            blockIdx.y*128, (blockIdx.x-8)*64);
}

// ---------------- Differential attention: fp16 + ldmatrix + reg prefetch ---
#define KH_STRIDE 36
#define VT_STRIDE 36
#define KVS 768
__global__ void __launch_bounds__(256) attn_tc(const __half* __restrict__ Q,
                                               const __half* __restrict__ KV,
                                               const float* __restrict__ lq1,
                                               const float* __restrict__ lk1,
                                               const float* __restrict__ lq2,
                                               const float* __restrict__ lk2,
                                               __half* __restrict__ O)
{
    __shared__ uint32_t Kh[64*KH_STRIDE];
    __shared__ uint32_t Vt[32*VT_STRIDE];

    const int b    = blockIdx.z;
    const int h    = blockIdx.y;
    const int warp = threadIdx.x >> 5;
    const int lane = threadIdx.x & 31;
    const int gr   = lane >> 2;
    const int gc   = lane & 3;
    const int qw   = blockIdx.x * 128 + warp * 16;

    const uint32_t khB = (uint32_t)__cvta_generic_to_shared(Kh);
    const uint32_t vtB = (uint32_t)__cvta_generic_to_shared(Vt);
    const int lb = (lane & 7) + ((lane >> 4) << 3), sb = (lane >> 3) & 1;

    float d1 = 0.f, d2 = 0.f;
    #pragma unroll
    for (int i = 0; i < HD; i++) {
        d1 = fmaf(lq1[h*HD+i], lk1[h*HD+i], d1);
        d2 = fmaf(lq2[h*HD+i], lk2[h*HD+i], d2);
    }
    const float lam = expf(d1) - expf(d2) + LAMBDA_INIT;

    uint32_t qh[2][2][4];
    {
        const uint32_t* q0 = (const uint32_t*)(Q + ((size_t)(b*NN + qw + gr))*(2*DIM)) + h*32;
        const uint32_t* q8 = q0 + 8*(2*DIM/2);
        #pragma unroll
        for (int half = 0; half < 2; half++) {
            #pragma unroll
            for (int kc = 0; kc < 2; kc++) {
                int off = half*16 + kc*8 + gc;
                qh[half][kc][0] = q0[off];
                qh[half][kc][1] = q8[off];
                qh[half][kc][2] = q0[off+4];
                qh[half][kc][3] = q8[off+4];
            }
        }
    }

    float o[2][4][4];
    #pragma unroll
    for (int hf=0; hf<2; hf++)
        #pragma unroll
        for (int n=0; n<4; n++)
            #pragma unroll
            for (int i=0; i<4; i++) o[hf][n][i] = 0.f;
    float lsum[2][2] = {{0.f,0.f},{0.f,0.f}};

    const int t = threadIdx.x;
    const int ki0 = t, ki1 = t + 256;          // K-chunk ids (key = i>>3, seg = i&7)
    const int vkey = t >> 2, vq = t & 3;       // V-chunk coords

    uint4 kreg0, kreg1, vreg;
    auto ldtile = [&](int k0) {
        kreg0 = *(const uint4*)(KV + ((size_t)(b*NN + k0 + (ki0>>3)))*KVS + h*HD2 + (ki0&7)*8);
        kreg1 = *(const uint4*)(KV + ((size_t)(b*NN + k0 + (ki1>>3)))*KVS + h*HD2 + (ki1&7)*8);
        vreg  = *(const uint4*)(KV + ((size_t)(b*NN + k0 + vkey))*KVS + 512 + h*HD + vq*8);
    };

    ldtile(0);
    for (int k0 = 0; k0 < NN; k0 += 64) {
        // store staged tile to smem
        *(uint4*)&Kh[(ki0>>3)*KH_STRIDE + (ki0&7)*4] = kreg0;
        *(uint4*)&Kh[(ki1>>3)*KH_STRIDE + (ki1&7)*4] = kreg1;
        {
            __half* Vh = (__half*)Vt;
            uint32_t w[4] = {vreg.x, vreg.y, vreg.z, vreg.w};
            #pragma unroll
            for (int j = 0; j < 4; j++) {
                __half2 hv = *(__half2*)&w[j];
                Vh[(vq*8 + j*2    )*(2*VT_STRIDE) + vkey] = __low2half(hv);
                Vh[(vq*8 + j*2 + 1)*(2*VT_STRIDE) + vkey] = __high2half(hv);
            }
        }
        __syncthreads();
        if (k0 + 64 < NN) ldtile(k0 + 64);   // prefetch next tile during compute

        uint32_t ph[2][4][4];
        #pragma unroll
        for (int half = 0; half < 2; half++) {
            float s[8][4];
            #pragma unroll
            for (int n=0;n<8;n++)
                #pragma unroll
                for (int i=0;i<4;i++) s[n][i] = 0.f;

            #pragma unroll
            for (int kc = 0; kc < 2; kc++) {
                const int kb = half*16 + kc*8;
                uint32_t bf[4][4];
                #pragma unroll
                for (int nj = 0; nj < 4; nj++)
                    ldsm4(bf[nj], khB + (((nj*16 + lb)*KH_STRIDE + kb + sb*4) << 2));
                #pragma unroll
                for (int n = 0; n < 8; n++)
                    mma_f16(s[n], qh[half][kc],
                            bf[n>>1][(n&1)*2], bf[n>>1][(n&1)*2+1]);
            }
            #pragma unroll
            for (int n = 0; n < 8; n++) {
                float p0 = ex2f(s[n][0]);
                float p1 = ex2f(s[n][1]);
                float p2 = ex2f(s[n][2]);
                float p3 = ex2f(s[n][3]);
                lsum[half][0] += p0 + p1;
                lsum[half][1] += p2 + p3;
                int ks = n >> 1, hi = (n & 1) * 2;
                ph[half][ks][hi    ] = packh2(p0, p1);
                ph[half][ks][hi + 1] = packh2(p2, p3);
            }
        }

        #pragma unroll
        for (int ks = 0; ks < 4; ks++) {
            uint32_t vf[2][4];
            #pragma unroll
            for (int nj = 0; nj < 2; nj++)
                ldsm4(vf[nj], vtB + (((nj*16 + lb)*VT_STRIDE + ks*8 + sb*4) << 2));
            #pragma unroll
            for (int n = 0; n < 4; n++) {
                uint32_t b0 = vf[n>>1][(n&1)*2], b1 = vf[n>>1][(n&1)*2+1];
                mma_f16(o[0][n], ph[0][ks], b0, b1);
                mma_f16(o[1][n], ph[1][ks], b0, b1);
            }
        }
        __syncthreads();
    }

    #pragma unroll
    for (int hf = 0; hf < 2; hf++) {
        #pragma unroll
        for (int r2 = 0; r2 < 2; r2++) {
            float v = lsum[hf][r2];
            v += __shfl_xor_sync(0xffffffffu, v, 1);
            v += __shfl_xor_sync(0xffffffffu, v, 2);
            lsum[hf][r2] = v;
        }
    }
    const float i1A = 1.f / lsum[0][0];
    const float i1B = 1.f / lsum[0][1];
    const float s2A = lam / lsum[1][0];
    const float s2B = lam / lsum[1][1];

    uint32_t* outA = (uint32_t*)(O + ((size_t)(b*NN + qw + gr    ))*DIM + h*HD);
    uint32_t* outB = (uint32_t*)(O + ((size_t)(b*NN + qw + gr + 8))*DIM + h*HD);
    #pragma unroll
    for (int n = 0; n < 4; n++) {
        outA[(n*8 + 2*gc) >> 1] = packh2(o[0][n][0]*i1A - o[1][n][0]*s2A,
                                         o[0][n][1]*i1A - o[1][n][1]*s2A);
        outB[(n*8 + 2*gc) >> 1] = packh2(o[0][n][2]*i1B - o[1][n][2]*s2B,
                                         o[0][n][3]*i1B - o[1][n][3]*s2B);
    }
}

// ---------------- launch ----------------------------------------------------
static void* symp(const void* sym) {
    void* p = nullptr;
    cudaGetSymbolAddress(&p, sym);
    return p;
}

extern "C" void kernel_launch(void* const* d_in, const int* in_sizes, int n_in,
                              void* d_out, int out_size)
{
    const float* drift = (const float*)d_in[0];
    const float* ocean = (const float*)d_in[1];
    const float* Wq    = (const float*)d_in[2];
    const float* Wk    = (const float*)d_in[3];
    const float* Wv    = (const float*)d_in[4];
    const float* Wo    = (const float*)d_in[5];
    const float* lq1   = (const float*)d_in[6];
    const float* lk1   = (const float*)d_in[7];
    const float* lq2   = (const float*)d_in[8];
    const float* lk2   = (const float*)d_in[9];
    const float* gamma = (const float*)d_in[10];
    const float* beta  = (const float*)d_in[11];
    const float* fc1w  = (const float*)d_in[12];
    const float* fc1b  = (const float*)d_in[13];
    const float* fc2w  = (const float*)d_in[14];
    const float* fc2b  = (const float*)d_in[15];
    float* out = (float*)d_out;

    __half* hw   = (__half*)symp(g_hw);
    __half* hx   = (__half*)symp(g_hx);
    __half* hQ   = (__half*)symp(g_hQ);
    __half* hKV  = (__half*)symp(g_hKV);
    __half* hatt = (__half*)symp(g_hatt);
    __half* hy   = (__half*)symp(g_hy);
    __half* hh   = (__half*)symp(g_hh);

    cudaFuncSetAttribute((const void*)gemm_qkv,         cudaFuncAttributeMaxDynamicSharedMemorySize, GEMM_SMEM(128,64));
    cudaFuncSetAttribute((const void*)gemm_h<1,64,64>,  cudaFuncAttributeMaxDynamicSharedMemorySize, GEMM_SMEM(64,64));
    cudaFuncSetAttribute((const void*)gemm_h<2,128,128>,cudaFuncAttributeMaxDynamicSharedMemorySize, GEMM_SMEM(128,128));
    cudaFuncSetAttribute((const void*)gemm_h<3,64,64>,  cudaFuncAttributeMaxDynamicSharedMemorySize, GEMM_SMEM(64,64));

    // 0) fused: LN1 + weight/ocean conversion (+ ocean passthrough)
    ln_cvt_kernel<<<512 + (HW_TOTAL/4 + 255)/256, 256>>>(
        drift, hx, gamma, beta,
        ocean, Wq, Wk, Wv, Wo, fc1w, fc2w, hw, out + (size_t)ROWS*DIM);
    // 1) fused Q + KV projections (one launch)
    gemm_qkv<<<dim3(20, ROWS/128), 256, GEMM_SMEM(128,64)>>>(hx, hw+WQ_OFF, hQ,
                                                             hw+OC_OFF, hw+WK_OFF, hKV);
    // 2) differential attention
    attn_tc<<<dim3(NN/128, HH, BB), 256>>>(hQ, hKV, lq1, lk1, lq2, lk2, hatt);
    // 3) drift2 = drift + att @ Wo^T -> out (fp32), BM=64 for occupancy
    gemm_h<1,64,64><<<dim3(256/64, ROWS/64), 256, GEMM_SMEM(64,64)>>>(hatt, hw+WO_OFF, nullptr, drift, out, 256, 256, 1.0f);
    // 4) y = LN(drift2) -> half
    ln_half<<<ROWS/8, 256>>>(out, hy, gamma, beta);
    // 5) h = gelu(y @ fc1^T + b1)
    gemm_h<2,128,128><<<dim3(1024/128, ROWS/128), 256, GEMM_SMEM(128,128)>>>(hy, hw+F1_OFF, fc1b, nullptr, hh, 1024, 256, 1.0f);
    // 6) drift_out = drift2 + h @ fc2^T + b2 (in-place on out), BM=64
    gemm_h<3,64,64><<<dim3(256/64, ROWS/64), 256, GEMM_SMEM(64,64)>>>(hh, hw+F2_OFF, fc2b, out, out, 256, 1024, 1.0f);
}

// round 15
// speedup vs baseline: 1.1124x; 1.1124x over previous
#include <cuda_runtime.h>
#include <cuda_fp16.h>
#include <math.h>
#include <stdint.h>

// Problem constants
#define BB    2
#define NN    2048
#define DIM   256
#define HH    8
#define HD    32
#define HD2   64
#define ROWS  (BB*NN)          // 4096
#define SCALE 0.17677669529663689f  // 32^-0.5
#define LOG2E 1.4426950408889634f
#define LAMBDA_INIT 0.1f
#define EPS   1e-5f

// ---------------- half weight/activation pool (static, no allocation) ------
#define OC_OFF   0u
#define WQ_OFF   1048576u
#define WK_OFF   1179648u      // Wk (512x256) then Wv (256x256) contiguous
#define WV_OFF   1310720u
#define WO_OFF   1376256u
#define F1_OFF   1441792u
#define F2_OFF   1703936u
#define HW_TOTAL 1966080u
__device__ __half g_hw [HW_TOTAL];     // ocean + all weights (fp16)
__device__ __half g_hx [ROWS*DIM];     // LN1 out
__device__ __half g_hQ [ROWS*2*DIM];   // Q (pre-scaled by SCALE*LOG2E)
__device__ __half g_hKV[ROWS*768];     // fused K(512) | V(256) per row
__device__ __half g_hatt[ROWS*DIM];
__device__ __half g_hy [ROWS*DIM];     // LN2 out
__device__ __half g_hh [ROWS*4*DIM];   // MLP hidden

// ---------------- helpers ---------------------------------------------------
__device__ __forceinline__ void mma_f16(float* d, const uint32_t* a,
                                        uint32_t b0, uint32_t b1) {
    asm volatile("mma.sync.aligned.m16n8k16.row.col.f32.f16.f16.f32 "
                 "{%0,%1,%2,%3},{%4,%5,%6,%7},{%8,%9},{%0,%1,%2,%3};"
                 : "+f"(d[0]), "+f"(d[1]), "+f"(d[2]), "+f"(d[3])
                 : "r"(a[0]), "r"(a[1]), "r"(a[2]), "r"(a[3]),
                   "r"(b0), "r"(b1));
}
__device__ __forceinline__ void ldsm4(uint32_t* r, uint32_t addr) {
    asm volatile("ldmatrix.sync.aligned.m8n8.x4.shared.b16 {%0,%1,%2,%3}, [%4];"
                 : "=r"(r[0]), "=r"(r[1]), "=r"(r[2]), "=r"(r[3]) : "r"(addr));
}
__device__ __forceinline__ uint32_t packh2(float x, float y) {
    __half2 h = __floats2half2_rn(x, y);
    return *reinterpret_cast<uint32_t*>(&h);
}
__device__ __forceinline__ float ex2f(float x) {
    float y;
    asm("ex2.approx.f32 %0, %1;" : "=f"(y) : "f"(x));
    return y;
}
__device__ __forceinline__ void cp16(uint32_t saddr, const void* g) {
    asm volatile("cp.async.cg.shared.global [%0], [%1], 16;\n" :: "r"(saddr), "l"(g));
}
__device__ __forceinline__ void cp_commit() { asm volatile("cp.async.commit_group;\n"); }
template<int N> __device__ __forceinline__ void cp_wait() {
    asm volatile("cp.async.wait_group %0;\n" :: "n"(N));
}

// ---------------- fused LN1 + fp32->fp16 conversion -------------------------
__global__ void __launch_bounds__(256) ln_cvt_kernel(
    const float* __restrict__ drift, __half* __restrict__ hx,
    const float* __restrict__ gamma, const float* __restrict__ beta,
    const float* __restrict__ oc,
    const float* __restrict__ wq, const float* __restrict__ wk,
    const float* __restrict__ wv, const float* __restrict__ wo,
    const float* __restrict__ f1, const float* __restrict__ f2,
    __half* __restrict__ dst, float* __restrict__ oout)
{
    if (blockIdx.x < 512) {
        int wid  = threadIdx.x >> 5;
        int lane = threadIdx.x & 31;
        int row  = blockIdx.x * 8 + wid;
        const float4* p = (const float4*)(drift + (size_t)row * DIM);
        float4 v0 = p[lane*2], v1 = p[lane*2+1];

        float s = v0.x+v0.y+v0.z+v0.w + v1.x+v1.y+v1.z+v1.w;
        #pragma unroll
        for (int o = 16; o; o >>= 1) s += __shfl_xor_sync(0xffffffffu, s, o);
        float mu = s * (1.0f/DIM);

        float d0x=v0.x-mu,d0y=v0.y-mu,d0z=v0.z-mu,d0w=v0.w-mu;
        float d1x=v1.x-mu,d1y=v1.y-mu,d1z=v1.z-mu,d1w=v1.w-mu;
        float q = d0x*d0x+d0y*d0y+d0z*d0z+d0w*d0w + d1x*d1x+d1y*d1y+d1z*d1z+d1w*d1w;
        #pragma unroll
        for (int o = 16; o; o >>= 1) q += __shfl_xor_sync(0xffffffffu, q, o);
        float rstd = rsqrtf(q * (1.0f/DIM) + EPS);

        const float4* gp = (const float4*)gamma;
        const float4* bp = (const float4*)beta;
        float4 g0 = gp[lane*2], g1 = gp[lane*2+1];
        float4 b0 = bp[lane*2], b1 = bp[lane*2+1];

        uint4 u;
        u.x = packh2(d0x*rstd*g0.x + b0.x, d0y*rstd*g0.y + b0.y);
        u.y = packh2(d0z*rstd*g0.z + b0.z, d0w*rstd*g0.w + b0.w);
        u.z = packh2(d1x*rstd*g1.x + b1.x, d1y*rstd*g1.y + b1.y);
        u.w = packh2(d1z*rstd*g1.z + b1.z, d1w*rstd*g1.w + b1.w);
        *(uint4*)&hx[(size_t)row*DIM + lane*8] = u;
    } else {
        uint32_t fi = ((uint32_t)(blockIdx.x - 512)*256u + threadIdx.x)*4u;
        if (fi >= HW_TOTAL) return;
        const float* src; uint32_t base;
        if      (fi < WQ_OFF) { src = oc; base = OC_OFF; }
        else if (fi < WK_OFF) { src = wq; base = WQ_OFF; }
        else if (fi < WV_OFF) { src = wk; base = WK_OFF; }
        else if (fi < WO_OFF) { src = wv; base = WV_OFF; }
        else if (fi < F1_OFF) { src = wo; base = WO_OFF; }
        else if (fi < F2_OFF) { src = f1; base = F1_OFF; }
        else                  { src = f2; base = F2_OFF; }
        float4 v = *(const float4*)&src[fi - base];
        if (fi < WQ_OFF) *(float4*)&oout[fi] = v;   // ocean passthrough (fp32)
        uint2 u = make_uint2(packh2(v.x, v.y), packh2(v.z, v.w));
        *(uint2*)&dst[fi] = u;
    }
}

// ---------------- LayerNorm standalone (for ln2) ----------------------------
__global__ void __launch_bounds__(256) ln_half(const float* __restrict__ in,
                                               __half* __restrict__ out,
                                               const float* __restrict__ gamma,
                                               const float* __restrict__ beta)
{
    int wid  = threadIdx.x >> 5;
    int lane = threadIdx.x & 31;
    int row  = blockIdx.x * 8 + wid;
    const float4* p = (const float4*)(in + (size_t)row * DIM);
    float4 v0 = p[lane*2], v1 = p[lane*2+1];

    float s = v0.x+v0.y+v0.z+v0.w + v1.x+v1.y+v1.z+v1.w;
    #pragma unroll
    for (int o = 16; o; o >>= 1) s += __shfl_xor_sync(0xffffffffu, s, o);
    float mu = s * (1.0f/DIM);

    float d0x=v0.x-mu,d0y=v0.y-mu,d0z=v0.z-mu,d0w=v0.w-mu;
    float d1x=v1.x-mu,d1y=v1.y-mu,d1z=v1.z-mu,d1w=v1.w-mu;
    float q = d0x*d0x+d0y*d0y+d0z*d0z+d0w*d0w + d1x*d1x+d1y*d1y+d1z*d1z+d1w*d1w;
    #pragma unroll
    for (int o = 16; o; o >>= 1) q += __shfl_xor_sync(0xffffffffu, q, o);
    float rstd = rsqrtf(q * (1.0f/DIM) + EPS);

    const float4* gp = (const float4*)gamma;
    const float4* bp = (const float4*)beta;
    float4 g0 = gp[lane*2], g1 = gp[lane*2+1];
    float4 b0 = bp[lane*2], b1 = bp[lane*2+1];

    uint4 u;
    u.x = packh2(d0x*rstd*g0.x + b0.x, d0y*rstd*g0.y + b0.y);
    u.y = packh2(d0z*rstd*g0.z + b0.z, d0w*rstd*g0.w + b0.w);
    u.z = packh2(d1x*rstd*g1.x + b1.x, d1y*rstd*g1.y + b1.y);
    u.w = packh2(d1z*rstd*g1.z + b1.z, d1w*rstd*g1.w + b1.w);
    *(uint4*)&out[(size_t)row*DIM + lane*8] = u;
}

// ---------------- fp16 GEMM core: cp.async 3-stage, ldmatrix ----------------
// C[M,N] = A[M,K] * B[N,K]^T. Tile 128xBN (BN=32/64/128), K-chunk 32 halves,
// 256 threads = 8 warps as 4(M) x 2(N); warp tile 32 x BN/2.
// EPI: 0 = *oscale -> half, 1 = +res -> float, 2 = gelu(.+bias) -> half,
//      3 = +bias+res -> float
#define GSTR 20
#define NSTAGE 3
#define GEMM_SMEM(BN) ((NSTAGE*(128+(BN))*GSTR)*4)
template<int EPI, int BN>
__device__ __forceinline__ void gemm_core(const __half* __restrict__ A,
                                          const __half* __restrict__ Bm,
                                          const float* __restrict__ bias,
                                          const float* __restrict__ res,
                                          void* __restrict__ Cout,
                                          int N, int K, float oscale,
                                          int m0, int n0)
{
    constexpr int NI = BN/16;       // n8 tiles per warp
    constexpr int NJ = BN/32;       // n16 ldsm tiles per warp
    constexpr int GSM_A = NSTAGE*128*GSTR;

    extern __shared__ uint32_t smu[];
    uint32_t* sA = smu;
    uint32_t* sB = smu + GSM_A;
    const uint32_t sA_base = (uint32_t)__cvta_generic_to_shared(sA);
    const uint32_t sB_base = (uint32_t)__cvta_generic_to_shared(sB);

    const int tid  = threadIdx.x;
    const int lane = tid & 31;
    const int warp = tid >> 5;
    const int gr   = lane >> 2;
    const int gc   = lane & 3;
    const int wm   = warp >> 1;
    const int wn   = warp & 1;

    const int lrow = tid >> 2, lseg = tid & 3;

    const int la = lane & 15,                 sa = lane >> 4;
    const int lb = (lane & 7) + ((lane >> 4) << 3), sb = (lane >> 3) & 1;

    float c[2][NI][4];
    #pragma unroll
    for (int mi=0; mi<2; mi++)
        #pragma unroll
        for (int ni=0; ni<NI; ni++)
            #pragma unroll
            for (int i=0; i<4; i++) c[mi][ni][i] = 0.f;

    auto fill = [&](int stage, int k0) {
        cp16(sA_base + (((stage*128 + lrow)*GSTR + lseg*4) << 2),
             A + (size_t)(m0 + lrow)*K + k0 + lseg*8);
        cp16(sA_base + (((stage*128 + lrow + 64)*GSTR + lseg*4) << 2),
             A + (size_t)(m0 + lrow + 64)*K + k0 + lseg*8);
        if (BN >= 64 || lrow < BN)
            cp16(sB_base + (((stage*BN + lrow)*GSTR + lseg*4) << 2),
                 Bm + (size_t)(n0 + lrow)*K + k0 + lseg*8);
        if (BN == 128)
            cp16(sB_base + (((stage*BN + lrow + 64)*GSTR + lseg*4) << 2),
                 Bm + (size_t)(n0 + lrow + 64)*K + k0 + lseg*8);
    };

    auto compute = [&](int stage) {
        const uint32_t aBase = sA_base + (((stage*128 + wm*32)*GSTR) << 2);
        const uint32_t bBase = sB_base + (((stage*BN + wn*(BN/2))*GSTR) << 2);
        #pragma unroll
        for (int kc = 0; kc < 2; kc++) {
            const int kb = kc*8;
            uint32_t af[2][4], bf[NJ][4];
            #pragma unroll
            for (int mi = 0; mi < 2; mi++)
                ldsm4(af[mi], aBase + (((mi*16 + la)*GSTR + kb + sa*4) << 2));
            #pragma unroll
            for (int nj = 0; nj < NJ; nj++)
                ldsm4(bf[nj], bBase + (((nj*16 + lb)*GSTR + kb + sb*4) << 2));
            #pragma unroll
            for (int mi = 0; mi < 2; mi++)
                #pragma unroll
                for (int ni = 0; ni < NI; ni++)
                    mma_f16(c[mi][ni], af[mi],
                            bf[ni>>1][(ni&1)*2], bf[ni>>1][(ni&1)*2+1]);
        }
    };

    const int nIter = K >> 5;
    fill(0, 0);  cp_commit();
    fill(1, 32); cp_commit();
    for (int it = 0; it < nIter; it++) {
        cp_wait<1>();
        __syncthreads();
        if (it + 2 < nIter) fill((it+2) % 3, (it+2)*32);
        cp_commit();
        compute(it % 3);
    }

    #pragma unroll
    for (int ni = 0; ni < NI; ni++) {
        const int col = n0 + wn*(BN/2) + ni*8 + 2*gc;
        float2 bi = make_float2(0.f, 0.f);
        if (EPI == 2 || EPI == 3) bi = *(const float2*)&bias[col];
        #pragma unroll
        for (int mi = 0; mi < 2; mi++) {
            const int row0 = m0 + wm*32 + mi*16 + gr;
            #pragma unroll
            for (int hh2 = 0; hh2 < 2; hh2++) {
                const int row = row0 + hh2*8;
                float2 v = make_float2(c[mi][ni][hh2*2], c[mi][ni][hh2*2+1]);
                if (EPI == 0) { v.x *= oscale; v.y *= oscale; }
                if (EPI == 2) {
                    v.x += bi.x; v.y += bi.y;
                    v.x = 0.5f*v.x*(1.0f + erff(v.x*0.7071067811865475f));
                    v.y = 0.5f*v.y*(1.0f + erff(v.y*0.7071067811865475f));
                }
                if (EPI == 3) { v.x += bi.x; v.y += bi.y; }
                if (EPI == 1 || EPI == 3) {
                    float2 r = *(const float2*)&res[(size_t)row*N + col];
                    v.x += r.x; v.y += r.y;
                }
                if (EPI == 0 || EPI == 2) {
                    ((uint32_t*)Cout)[((size_t)row*N + col) >> 1] = packh2(v.x, v.y);
                } else {
                    *(float2*)&((float*)Cout)[(size_t)row*N + col] = v;
                }
            }
        }
    }
}

template<int EPI, int BN>
__global__ void __launch_bounds__(256) gemm_h(const __half* __restrict__ A,
                                              const __half* __restrict__ Bm,
                                              const float* __restrict__ bias,
                                              const float* __restrict__ res,
                                              void* __restrict__ Cout,
                                              int N, int K, float oscale)
{
    gemm_core<EPI,BN>(A, Bm, bias, res, Cout, N, K, oscale,
                      blockIdx.y*128, blockIdx.x*BN);
}

// fused Q + KV projection: blocks x<8 -> Q (N=512), x>=8 -> KV (N=768)
__global__ void __launch_bounds__(256) gemm_qkv(const __half* __restrict__ x,
                                                const __half* __restrict__ wq,
                                                __half* __restrict__ Qout,
                                                const __half* __restrict__ oc,
                                                const __half* __restrict__ wkv,
                                                __half* __restrict__ KVout)
{
    if (blockIdx.x < 8)
        gemm_core<0,64>(x, wq, nullptr, nullptr, Qout, 512, 256, SCALE*LOG2E,
                        blockIdx.y*128, blockIdx.x*64);
    else
        gemm_core<0,64>(oc, wkv, nullptr, nullptr, KVout, 768, 256, 1.0f,
                        blockIdx.y*128, (blockIdx.x-8)*64);
}

// ---------------- Differential attention: fp16 + ldmatrix fragments --------
// (R12 version — no register prefetch; that regressed in R14)
#define KH_STRIDE 36
#define VT_STRIDE 36
#define KVS 768
__global__ void __launch_bounds__(256) attn_tc(const __half* __restrict__ Q,
                                               const __half* __restrict__ KV,
                                               const float* __restrict__ lq1,
                                               const float* __restrict__ lk1,
                                               const float* __restrict__ lq2,
                                               const float* __restrict__ lk2,
                                               __half* __restrict__ O)
{
    __shared__ uint32_t Kh[64*KH_STRIDE];
    __shared__ uint32_t Vt[32*VT_STRIDE];

    const int b    = blockIdx.z;
    const int h    = blockIdx.y;
    const int warp = threadIdx.x >> 5;
    const int lane = threadIdx.x & 31;
    const int gr   = lane >> 2;
    const int gc   = lane & 3;
    const int qw   = blockIdx.x * 128 + warp * 16;

    const uint32_t khB = (uint32_t)__cvta_generic_to_shared(Kh);
    const uint32_t vtB = (uint32_t)__cvta_generic_to_shared(Vt);
    const int lb = (lane & 7) + ((lane >> 4) << 3), sb = (lane >> 3) & 1;

    float d1 = 0.f, d2 = 0.f;
    #pragma unroll
    for (int i = 0; i < HD; i++) {
        d1 = fmaf(lq1[h*HD+i], lk1[h*HD+i], d1);
        d2 = fmaf(lq2[h*HD+i], lk2[h*HD+i], d2);
    }
    const float lam = expf(d1) - expf(d2) + LAMBDA_INIT;

    uint32_t qh[2][2][4];
    {
        const uint32_t* q0 = (const uint32_t*)(Q + ((size_t)(b*NN + qw + gr))*(2*DIM)) + h*32;
        const uint32_t* q8 = q0 + 8*(2*DIM/2);
        #pragma unroll
        for (int half = 0; half < 2; half++) {
            #pragma unroll
            for (int kc = 0; kc < 2; kc++) {
                int off = half*16 + kc*8 + gc;
                qh[half][kc][0] = q0[off];
                qh[half][kc][1] = q8[off];
                qh[half][kc][2] = q0[off+4];
                qh[half][kc][3] = q8[off+4];
            }
        }
    }

    float o[2][4][4];
    #pragma unroll
    for (int hf=0; hf<2; hf++)
        #pragma unroll
        for (int n=0; n<4; n++)
            #pragma unroll
            for (int i=0; i<4; i++) o[hf][n][i] = 0.f;
    float lsum[2][2] = {{0.f,0.f},{0.f,0.f}};

    const int t = threadIdx.x;
    for (int k0 = 0; k0 < NN; k0 += 64) {
        __syncthreads();
        #pragma unroll
        for (int it = 0; it < 2; it++) {
            int i = t + it*256;
            int key = i >> 3, seg = i & 7;
            uint4 v = *(const uint4*)(KV + ((size_t)(b*NN + k0 + key))*KVS + h*HD2 + seg*8);
            *(uint4*)&Kh[key*KH_STRIDE + seg*4] = v;
        }
        {
            int key = t >> 2, q = t & 3;
            uint4 v = *(const uint4*)(KV + ((size_t)(b*NN + k0 + key))*KVS + 512 + h*HD + q*8);
            __half* Vh = (__half*)Vt;
            uint32_t w[4] = {v.x, v.y, v.z, v.w};
            #pragma unroll
            for (int j = 0; j < 4; j++) {
                __half2 hv = *(__half2*)&w[j];
                Vh[(q*8 + j*2    )*(2*VT_STRIDE) + key] = __low2half(hv);
                Vh[(q*8 + j*2 + 1)*(2*VT_STRIDE) + key] = __high2half(hv);
            }
        }
        __syncthreads();

        uint32_t ph[2][4][4];
        #pragma unroll
        for (int half = 0; half < 2; half++) {
            float s[8][4];
            #pragma unroll
            for (int n=0;n<8;n++)
                #pragma unroll
                for (int i=0;i<4;i++) s[n][i] = 0.f;

            #pragma unroll
            for (int kc = 0; kc < 2; kc++) {
                const int kb = half*16 + kc*8;
                uint32_t bf[4][4];
                #pragma unroll
                for (int nj = 0; nj < 4; nj++)
                    ldsm4(bf[nj], khB + (((nj*16 + lb)*KH_STRIDE + kb + sb*4) << 2));
                #pragma unroll
                for (int n = 0; n < 8; n++)
                    mma_f16(s[n], qh[half][kc],
                            bf[n>>1][(n&1)*2], bf[n>>1][(n&1)*2+1]);
            }
            #pragma unroll
            for (int n = 0; n < 8; n++) {
                float p0 = ex2f(s[n][0]);
                float p1 = ex2f(s[n][1]);
                float p2 = ex2f(s[n][2]);
                float p3 = ex2f(s[n][3]);
                lsum[half][0] += p0 + p1;
                lsum[half][1] += p2 + p3;
                int ks = n >> 1, hi = (n & 1) * 2;
                ph[half][ks][hi    ] = packh2(p0, p1);
                ph[half][ks][hi + 1] = packh2(p2, p3);
            }
        }

        #pragma unroll
        for (int ks = 0; ks < 4; ks++) {
            uint32_t vf[2][4];
            #pragma unroll
            for (int nj = 0; nj < 2; nj++)
                ldsm4(vf[nj], vtB + (((nj*16 + lb)*VT_STRIDE + ks*8 + sb*4) << 2));
            #pragma unroll
            for (int n = 0; n < 4; n++) {
                uint32_t b0 = vf[n>>1][(n&1)*2], b1 = vf[n>>1][(n&1)*2+1];
                mma_f16(o[0][n], ph[0][ks], b0, b1);
                mma_f16(o[1][n], ph[1][ks], b0, b1);
            }
        }
    }

    #pragma unroll
    for (int hf = 0; hf < 2; hf++) {
        #pragma unroll
        for (int r2 = 0; r2 < 2; r2++) {
            float v = lsum[hf][r2];
            v += __shfl_xor_sync(0xffffffffu, v, 1);
            v += __shfl_xor_sync(0xffffffffu, v, 2);
            lsum[hf][r2] = v;
        }
    }
    const float i1A = 1.f / lsum[0][0];
    const float i1B = 1.f / lsum[0][1];
    const float s2A = lam / lsum[1][0];
    const float s2B = lam / lsum[1][1];

    uint32_t* outA = (uint32_t*)(O + ((size_t)(b*NN + qw + gr    ))*DIM + h*HD);
    uint32_t* outB = (uint32_t*)(O + ((size_t)(b*NN + qw + gr + 8))*DIM + h*HD);
    #pragma unroll
    for (int n = 0; n < 4; n++) {
        outA[(n*8 + 2*gc) >> 1] = packh2(o[0][n][0]*i1A - o[1][n][0]*s2A,
                                         o[0][n][1]*i1A - o[1][n][1]*s2A);
        outB[(n*8 + 2*gc) >> 1] = packh2(o[0][n][2]*i1B - o[1][n][2]*s2B,
                                         o[0][n][3]*i1B - o[1][n][3]*s2B);
    }
}

// ---------------- launch ----------------------------------------------------
static void* symp(const void* sym) {
    void* p = nullptr;
    cudaGetSymbolAddress(&p, sym);
    return p;
}

extern "C" void kernel_launch(void* const* d_in, const int* in_sizes, int n_in,
                              void* d_out, int out_size)
{
    const float* drift = (const float*)d_in[0];
    const float* ocean = (const float*)d_in[1];
    const float* Wq    = (const float*)d_in[2];
    const float* Wk    = (const float*)d_in[3];
    const float* Wv    = (const float*)d_in[4];
    const float* Wo    = (const float*)d_in[5];
    const float* lq1   = (const float*)d_in[6];
    const float* lk1   = (const float*)d_in[7];
    const float* lq2   = (const float*)d_in[8];
    const float* lk2   = (const float*)d_in[9];
    const float* gamma = (const float*)d_in[10];
    const float* beta  = (const float*)d_in[11];
    const float* fc1w  = (const float*)d_in[12];
    const float* fc1b  = (const float*)d_in[13];
    const float* fc2w  = (const float*)d_in[14];
    const float* fc2b  = (const float*)d_in[15];
    float* out = (float*)d_out;

    __half* hw   = (__half*)symp(g_hw);
    __half* hx   = (__half*)symp(g_hx);
    __half* hQ   = (__half*)symp(g_hQ);
    __half* hKV  = (__half*)symp(g_hKV);
    __half* hatt = (__half*)symp(g_hatt);
    __half* hy   = (__half*)symp(g_hy);
    __half* hh   = (__half*)symp(g_hh);

    cudaFuncSetAttribute((const void*)gemm_qkv,      cudaFuncAttributeMaxDynamicSharedMemorySize, GEMM_SMEM(64));
    cudaFuncSetAttribute((const void*)gemm_h<1,32>,  cudaFuncAttributeMaxDynamicSharedMemorySize, GEMM_SMEM(32));
    cudaFuncSetAttribute((const void*)gemm_h<2,128>, cudaFuncAttributeMaxDynamicSharedMemorySize, GEMM_SMEM(128));
    cudaFuncSetAttribute((const void*)gemm_h<3,32>,  cudaFuncAttributeMaxDynamicSharedMemorySize, GEMM_SMEM(32));

    // 0) fused: LN1 + weight/ocean conversion (+ ocean passthrough)
    ln_cvt_kernel<<<512 + (HW_TOTAL/4 + 255)/256, 256>>>(
        drift, hx, gamma, beta,
        ocean, Wq, Wk, Wv, Wo, fc1w, fc2w, hw, out + (size_t)ROWS*DIM);
    // 1) fused Q + KV projections (one launch)
    gemm_qkv<<<dim3(20, ROWS/128), 256, GEMM_SMEM(64)>>>(hx, hw+WQ_OFF, hQ,
                                                         hw+OC_OFF, hw+WK_OFF, hKV);
    // 2) differential attention
    attn_tc<<<dim3(NN/128, HH, BB), 256>>>(hQ, hKV, lq1, lk1, lq2, lk2, hatt);
    // 3) drift2 = drift + att @ Wo^T -> out (fp32), BN=32 for occupancy
    gemm_h<1,32><<<dim3(256/32, ROWS/128), 256, GEMM_SMEM(32)>>>(hatt, hw+WO_OFF, nullptr, drift, out, 256, 256, 1.0f);
    // 4) y = LN(drift2) -> half
    ln_half<<<ROWS/8, 256>>>(out, hy, gamma, beta);
    // 5) h = gelu(y @ fc1^T + b1)
    gemm_h<2,128><<<dim3(1024/128, ROWS/128), 256, GEMM_SMEM(128)>>>(hy, hw+F1_OFF, fc1b, nullptr, hh, 1024, 256, 1.0f);
    // 6) drift_out = drift2 + h @ fc2^T + b2 (in-place on out), BN=32
    gemm_h<3,32><<<dim3(256/32, ROWS/128), 256, GEMM_SMEM(32)>>>(hh, hw+F2_OFF, fc2b, out, out, 256, 1024, 1.0f);
}

// round 16
// speedup vs baseline: 1.1591x; 1.0419x over previous
#include <cuda_runtime.h>
#include <cuda_fp16.h>
#include <math.h>
#include <stdint.h>

// Problem constants
#define BB    2
#define NN    2048
#define DIM   256
#define HH    8
#define HD    32
#define HD2   64
#define ROWS  (BB*NN)          // 4096
#define SCALE 0.17677669529663689f  // 32^-0.5
#define LOG2E 1.4426950408889634f
#define LAMBDA_INIT 0.1f
#define EPS   1e-5f

// ---------------- half weight/activation pool (static, no allocation) ------
#define OC_OFF   0u
#define WQ_OFF   1048576u
#define WK_OFF   1179648u      // Wk (512x256) then Wv (256x256) contiguous
#define WV_OFF   1310720u
#define WO_OFF   1376256u
#define F1_OFF   1441792u
#define F2_OFF   1703936u
#define HW_TOTAL 1966080u
__device__ __half g_hw [HW_TOTAL];     // ocean + all weights (fp16)
__device__ __half g_hx [ROWS*DIM];     // LN1 out
__device__ __half g_hQ [ROWS*2*DIM];   // Q (pre-scaled by SCALE*LOG2E)
__device__ __half g_hKV[ROWS*768];     // fused K(512) | V(256) per row
__device__ __half g_hatt[ROWS*DIM];
__device__ __half g_hy [ROWS*DIM];     // LN2 out
__device__ __half g_hh [ROWS*4*DIM];   // MLP hidden

// ---------------- helpers ---------------------------------------------------
__device__ __forceinline__ void mma_f16(float* d, const uint32_t* a,
                                        uint32_t b0, uint32_t b1) {
    asm volatile("mma.sync.aligned.m16n8k16.row.col.f32.f16.f16.f32 "
                 "{%0,%1,%2,%3},{%4,%5,%6,%7},{%8,%9},{%0,%1,%2,%3};"
                 : "+f"(d[0]), "+f"(d[1]), "+f"(d[2]), "+f"(d[3])
                 : "r"(a[0]), "r"(a[1]), "r"(a[2]), "r"(a[3]),
                   "r"(b0), "r"(b1));
}
__device__ __forceinline__ void ldsm4(uint32_t* r, uint32_t addr) {
    asm volatile("ldmatrix.sync.aligned.m8n8.x4.shared.b16 {%0,%1,%2,%3}, [%4];"
                 : "=r"(r[0]), "=r"(r[1]), "=r"(r[2]), "=r"(r[3]) : "r"(addr));
}
__device__ __forceinline__ uint32_t packh2(float x, float y) {
    __half2 h = __floats2half2_rn(x, y);
    return *reinterpret_cast<uint32_t*>(&h);
}
__device__ __forceinline__ float ex2f(float x) {
    float y;
    asm("ex2.approx.f32 %0, %1;" : "=f"(y) : "f"(x));
    return y;
}
__device__ __forceinline__ void cp16(uint32_t saddr, const void* g) {
    asm volatile("cp.async.cg.shared.global [%0], [%1], 16;\n" :: "r"(saddr), "l"(g));
}
__device__ __forceinline__ void cp_commit() { asm volatile("cp.async.commit_group;\n"); }
template<int N> __device__ __forceinline__ void cp_wait() {
    asm volatile("cp.async.wait_group %0;\n" :: "n"(N));
}

// ---------------- fused LN1 + fp32->fp16 conversion -------------------------
__global__ void __launch_bounds__(256) ln_cvt_kernel(
    const float* __restrict__ drift, __half* __restrict__ hx,
    const float* __restrict__ gamma, const float* __restrict__ beta,
    const float* __restrict__ oc,
    const float* __restrict__ wq, const float* __restrict__ wk,
    const float* __restrict__ wv, const float* __restrict__ wo,
    const float* __restrict__ f1, const float* __restrict__ f2,
    __half* __restrict__ dst, float* __restrict__ oout)
{
    if (blockIdx.x < 512) {
        int wid  = threadIdx.x >> 5;
        int lane = threadIdx.x & 31;
        int row  = blockIdx.x * 8 + wid;
        const float4* p = (const float4*)(drift + (size_t)row * DIM);
        float4 v0 = p[lane*2], v1 = p[lane*2+1];

        float s = v0.x+v0.y+v0.z+v0.w + v1.x+v1.y+v1.z+v1.w;
        #pragma unroll
        for (int o = 16; o; o >>= 1) s += __shfl_xor_sync(0xffffffffu, s, o);
        float mu = s * (1.0f/DIM);

        float d0x=v0.x-mu,d0y=v0.y-mu,d0z=v0.z-mu,d0w=v0.w-mu;
        float d1x=v1.x-mu,d1y=v1.y-mu,d1z=v1.z-mu,d1w=v1.w-mu;
        float q = d0x*d0x+d0y*d0y+d0z*d0z+d0w*d0w + d1x*d1x+d1y*d1y+d1z*d1z+d1w*d1w;
        #pragma unroll
        for (int o = 16; o; o >>= 1) q += __shfl_xor_sync(0xffffffffu, q, o);
        float rstd = rsqrtf(q * (1.0f/DIM) + EPS);

        const float4* gp = (const float4*)gamma;
        const float4* bp = (const float4*)beta;
        float4 g0 = gp[lane*2], g1 = gp[lane*2+1];
        float4 b0 = bp[lane*2], b1 = bp[lane*2+1];

        uint4 u;
        u.x = packh2(d0x*rstd*g0.x + b0.x, d0y*rstd*g0.y + b0.y);
        u.y = packh2(d0z*rstd*g0.z + b0.z, d0w*rstd*g0.w + b0.w);
        u.z = packh2(d1x*rstd*g1.x + b1.x, d1y*rstd*g1.y + b1.y);
        u.w = packh2(d1z*rstd*g1.z + b1.z, d1w*rstd*g1.w + b1.w);
        *(uint4*)&hx[(size_t)row*DIM + lane*8] = u;
    } else {
        uint32_t fi = ((uint32_t)(blockIdx.x - 512)*256u + threadIdx.x)*4u;
        if (fi >= HW_TOTAL) return;
        const float* src; uint32_t base;
        if      (fi < WQ_OFF) { src = oc; base = OC_OFF; }
        else if (fi < WK_OFF) { src = wq; base = WQ_OFF; }
        else if (fi < WV_OFF) { src = wk; base = WK_OFF; }
        else if (fi < WO_OFF) { src = wv; base = WV_OFF; }
        else if (fi < F1_OFF) { src = wo; base = WO_OFF; }
        else if (fi < F2_OFF) { src = f1; base = F1_OFF; }
        else                  { src = f2; base = F2_OFF; }
        float4 v = *(const float4*)&src[fi - base];
        if (fi < WQ_OFF) *(float4*)&oout[fi] = v;   // ocean passthrough (fp32)
        uint2 u = make_uint2(packh2(v.x, v.y), packh2(v.z, v.w));
        *(uint2*)&dst[fi] = u;
    }
}

// ---------------- LayerNorm standalone (for ln2) ----------------------------
__global__ void __launch_bounds__(256) ln_half(const float* __restrict__ in,
                                               __half* __restrict__ out,
                                               const float* __restrict__ gamma,
                                               const float* __restrict__ beta)
{
    int wid  = threadIdx.x >> 5;
    int lane = threadIdx.x & 31;
    int row  = blockIdx.x * 8 + wid;
    const float4* p = (const float4*)(in + (size_t)row * DIM);
    float4 v0 = p[lane*2], v1 = p[lane*2+1];

    float s = v0.x+v0.y+v0.z+v0.w + v1.x+v1.y+v1.z+v1.w;
    #pragma unroll
    for (int o = 16; o; o >>= 1) s += __shfl_xor_sync(0xffffffffu, s, o);
    float mu = s * (1.0f/DIM);

    float d0x=v0.x-mu,d0y=v0.y-mu,d0z=v0.z-mu,d0w=v0.w-mu;
    float d1x=v1.x-mu,d1y=v1.y-mu,d1z=v1.z-mu,d1w=v1.w-mu;
    float q = d0x*d0x+d0y*d0y+d0z*d0z+d0w*d0w + d1x*d1x+d1y*d1y+d1z*d1z+d1w*d1w;
    #pragma unroll
    for (int o = 16; o; o >>= 1) q += __shfl_xor_sync(0xffffffffu, q, o);
    float rstd = rsqrtf(q * (1.0f/DIM) + EPS);

    const float4* gp = (const float4*)gamma;
    const float4* bp = (const float4*)beta;
    float4 g0 = gp[lane*2], g1 = gp[lane*2+1];
    float4 b0 = bp[lane*2], b1 = bp[lane*2+1];

    uint4 u;
    u.x = packh2(d0x*rstd*g0.x + b0.x, d0y*rstd*g0.y + b0.y);
    u.y = packh2(d0z*rstd*g0.z + b0.z, d0w*rstd*g0.w + b0.w);
    u.z = packh2(d1x*rstd*g1.x + b1.x, d1y*rstd*g1.y + b1.y);
    u.w = packh2(d1z*rstd*g1.z + b1.z, d1w*rstd*g1.w + b1.w);
    *(uint4*)&out[(size_t)row*DIM + lane*8] = u;
}

// ---------------- fp16 GEMM core: cp.async 3-stage, ldmatrix ----------------
// (R12 configuration — measured best)
#define GSTR 20
#define NSTAGE 3
#define GEMM_SMEM(BN) ((NSTAGE*(128+(BN))*GSTR)*4)
template<int EPI, int BN>
__device__ __forceinline__ void gemm_core(const __half* __restrict__ A,
                                          const __half* __restrict__ Bm,
                                          const float* __restrict__ bias,
                                          const float* __restrict__ res,
                                          void* __restrict__ Cout,
                                          int N, int K, float oscale,
                                          int m0, int n0)
{
    constexpr int NI = BN/16;
    constexpr int NJ = BN/32;
    constexpr int GSM_A = NSTAGE*128*GSTR;

    extern __shared__ uint32_t smu[];
    uint32_t* sA = smu;
    uint32_t* sB = smu + GSM_A;
    const uint32_t sA_base = (uint32_t)__cvta_generic_to_shared(sA);
    const uint32_t sB_base = (uint32_t)__cvta_generic_to_shared(sB);

    const int tid  = threadIdx.x;
    const int lane = tid & 31;
    const int warp = tid >> 5;
    const int gr   = lane >> 2;
    const int gc   = lane & 3;
    const int wm   = warp >> 1;
    const int wn   = warp & 1;

    const int lrow = tid >> 2, lseg = tid & 3;

    const int la = lane & 15,                 sa = lane >> 4;
    const int lb = (lane & 7) + ((lane >> 4) << 3), sb = (lane >> 3) & 1;

    float c[2][NI][4];
    #pragma unroll
    for (int mi=0; mi<2; mi++)
        #pragma unroll
        for (int ni=0; ni<NI; ni++)
            #pragma unroll
            for (int i=0; i<4; i++) c[mi][ni][i] = 0.f;

    auto fill = [&](int stage, int k0) {
        cp16(sA_base + (((stage*128 + lrow)*GSTR + lseg*4) << 2),
             A + (size_t)(m0 + lrow)*K + k0 + lseg*8);
        cp16(sA_base + (((stage*128 + lrow + 64)*GSTR + lseg*4) << 2),
             A + (size_t)(m0 + lrow + 64)*K + k0 + lseg*8);
        cp16(sB_base + (((stage*BN + lrow)*GSTR + lseg*4) << 2),
             Bm + (size_t)(n0 + lrow)*K + k0 + lseg*8);
        if (BN == 128)
            cp16(sB_base + (((stage*BN + lrow + 64)*GSTR + lseg*4) << 2),
                 Bm + (size_t)(n0 + lrow + 64)*K + k0 + lseg*8);
    };

    auto compute = [&](int stage) {
        const uint32_t aBase = sA_base + (((stage*128 + wm*32)*GSTR) << 2);
        const uint32_t bBase = sB_base + (((stage*BN + wn*(BN/2))*GSTR) << 2);
        #pragma unroll
        for (int kc = 0; kc < 2; kc++) {
            const int kb = kc*8;
            uint32_t af[2][4], bf[NJ][4];
            #pragma unroll
            for (int mi = 0; mi < 2; mi++)
                ldsm4(af[mi], aBase + (((mi*16 + la)*GSTR + kb + sa*4) << 2));
            #pragma unroll
            for (int nj = 0; nj < NJ; nj++)
                ldsm4(bf[nj], bBase + (((nj*16 + lb)*GSTR + kb + sb*4) << 2));
            #pragma unroll
            for (int mi = 0; mi < 2; mi++)
                #pragma unroll
                for (int ni = 0; ni < NI; ni++)
                    mma_f16(c[mi][ni], af[mi],
                            bf[ni>>1][(ni&1)*2], bf[ni>>1][(ni&1)*2+1]);
        }
    };

    const int nIter = K >> 5;
    fill(0, 0);  cp_commit();
    fill(1, 32); cp_commit();
    for (int it = 0; it < nIter; it++) {
        cp_wait<1>();
        __syncthreads();
        if (it + 2 < nIter) fill((it+2) % 3, (it+2)*32);
        cp_commit();
        compute(it % 3);
    }

    #pragma unroll
    for (int ni = 0; ni < NI; ni++) {
        const int col = n0 + wn*(BN/2) + ni*8 + 2*gc;
        float2 bi = make_float2(0.f, 0.f);
        if (EPI == 2 || EPI == 3) bi = *(const float2*)&bias[col];
        #pragma unroll
        for (int mi = 0; mi < 2; mi++) {
            const int row0 = m0 + wm*32 + mi*16 + gr;
            #pragma unroll
            for (int hh2 = 0; hh2 < 2; hh2++) {
                const int row = row0 + hh2*8;
                float2 v = make_float2(c[mi][ni][hh2*2], c[mi][ni][hh2*2+1]);
                if (EPI == 0) { v.x *= oscale; v.y *= oscale; }
                if (EPI == 2) {
                    v.x += bi.x; v.y += bi.y;
                    v.x = 0.5f*v.x*(1.0f + erff(v.x*0.7071067811865475f));
                    v.y = 0.5f*v.y*(1.0f + erff(v.y*0.7071067811865475f));
                }
                if (EPI == 3) { v.x += bi.x; v.y += bi.y; }
                if (EPI == 1 || EPI == 3) {
                    float2 r = *(const float2*)&res[(size_t)row*N + col];
                    v.x += r.x; v.y += r.y;
                }
                if (EPI == 0 || EPI == 2) {
                    ((uint32_t*)Cout)[((size_t)row*N + col) >> 1] = packh2(v.x, v.y);
                } else {
                    *(float2*)&((float*)Cout)[(size_t)row*N + col] = v;
                }
            }
        }
    }
}

template<int EPI, int BN>
__global__ void __launch_bounds__(256) gemm_h(const __half* __restrict__ A,
                                              const __half* __restrict__ Bm,
                                              const float* __restrict__ bias,
                                              const float* __restrict__ res,
                                              void* __restrict__ Cout,
                                              int N, int K, float oscale)
{
    gemm_core<EPI,BN>(A, Bm, bias, res, Cout, N, K, oscale,
                      blockIdx.y*128, blockIdx.x*BN);
}

// fused Q + KV projection: blocks x<8 -> Q (N=512), x>=8 -> KV (N=768)
__global__ void __launch_bounds__(256) gemm_qkv(const __half* __restrict__ x,
                                                const __half* __restrict__ wq,
                                                __half* __restrict__ Qout,
                                                const __half* __restrict__ oc,
                                                const __half* __restrict__ wkv,
                                                __half* __restrict__ KVout)
{
    if (blockIdx.x < 8)
        gemm_core<0,64>(x, wq, nullptr, nullptr, Qout, 512, 256, SCALE*LOG2E,
                        blockIdx.y*128, blockIdx.x*64);
    else
        gemm_core<0,64>(oc, wkv, nullptr, nullptr, KVout, 768, 256, 1.0f,
                        blockIdx.y*128, (blockIdx.x-8)*64);
}

// ---------------- Differential attention: cp.async double-buffered K -------
#define KH_STRIDE 36
#define VT_STRIDE 36
#define KVS 768
__global__ void __launch_bounds__(256) attn_tc(const __half* __restrict__ Q,
                                               const __half* __restrict__ KV,
                                               const float* __restrict__ lq1,
                                               const float* __restrict__ lk1,
                                               const float* __restrict__ lq2,
                                               const float* __restrict__ lk2,
                                               __half* __restrict__ O)
{
    __shared__ uint32_t Kh[2*64*KH_STRIDE];   // double-buffered K tiles
    __shared__ uint32_t Vt[32*VT_STRIDE];     // transposed V (single buffer)

    const int b    = blockIdx.z;
    const int h    = blockIdx.y;
    const int warp = threadIdx.x >> 5;
    const int lane = threadIdx.x & 31;
    const int gr   = lane >> 2;
    const int gc   = lane & 3;
    const int qw   = blockIdx.x * 128 + warp * 16;

    const uint32_t khB = (uint32_t)__cvta_generic_to_shared(Kh);
    const uint32_t vtB = (uint32_t)__cvta_generic_to_shared(Vt);
    const int lb = (lane & 7) + ((lane >> 4) << 3), sb = (lane >> 3) & 1;

    float d1 = 0.f, d2 = 0.f;
    #pragma unroll
    for (int i = 0; i < HD; i++) {
        d1 = fmaf(lq1[h*HD+i], lk1[h*HD+i], d1);
        d2 = fmaf(lq2[h*HD+i], lk2[h*HD+i], d2);
    }
    const float lam = expf(d1) - expf(d2) + LAMBDA_INIT;

    uint32_t qh[2][2][4];
    {
        const uint32_t* q0 = (const uint32_t*)(Q + ((size_t)(b*NN + qw + gr))*(2*DIM)) + h*32;
        const uint32_t* q8 = q0 + 8*(2*DIM/2);
        #pragma unroll
        for (int half = 0; half < 2; half++) {
            #pragma unroll
            for (int kc = 0; kc < 2; kc++) {
                int off = half*16 + kc*8 + gc;
                qh[half][kc][0] = q0[off];
                qh[half][kc][1] = q8[off];
                qh[half][kc][2] = q0[off+4];
                qh[half][kc][3] = q8[off+4];
            }
        }
    }

    float o[2][4][4];
    #pragma unroll
    for (int hf=0; hf<2; hf++)
        #pragma unroll
        for (int n=0; n<4; n++)
            #pragma unroll
            for (int i=0; i<4; i++) o[hf][n][i] = 0.f;
    float lsum[2][2] = {{0.f,0.f},{0.f,0.f}};

    const int t   = threadIdx.x;
    const int ki0 = t, ki1 = t + 256;          // K chunk ids: key=i>>3, seg=i&7
    const int vkey = t >> 2, vq = t & 3;       // V chunk coords

    auto fillK = [&](int k0, int buf) {
        const __half* base = KV + ((size_t)(b*NN + k0))*KVS + h*HD2;
        cp16(khB + (((buf*64 + (ki0>>3))*KH_STRIDE + (ki0&7)*4) << 2),
             base + (size_t)(ki0>>3)*KVS + (ki0&7)*8);
        cp16(khB + (((buf*64 + (ki1>>3))*KH_STRIDE + (ki1&7)*4) << 2),
             base + (size_t)(ki1>>3)*KVS + (ki1&7)*8);
    };

    uint4 vreg;
    auto ldV = [&](int k0) {
        vreg = *(const uint4*)(KV + ((size_t)(b*NN + k0 + vkey))*KVS + 512 + h*HD + vq*8);
    };

    fillK(0, 0); cp_commit();
    ldV(0);

    for (int tt = 0; tt < NN/64; tt++) {
        __syncthreads();                    // prior compute finished reading Vt/Kh
        // store V transform (from prefetched reg)
        {
            __half* Vh = (__half*)Vt;
            uint32_t w[4] = {vreg.x, vreg.y, vreg.z, vreg.w};
            #pragma unroll
            for (int j = 0; j < 4; j++) {
                __half2 hv = *(__half2*)&w[j];
                Vh[(vq*8 + j*2    )*(2*VT_STRIDE) + vkey] = __low2half(hv);
                Vh[(vq*8 + j*2 + 1)*(2*VT_STRIDE) + vkey] = __high2half(hv);
            }
        }
        cp_wait<0>();                       // K(tt) landed
        if (tt + 1 < NN/64) {               // launch next tile's loads
            fillK((tt+1)*64, (tt+1) & 1);
            cp_commit();
            ldV((tt+1)*64);
        }
        __syncthreads();                    // Vt + Kh visible to all

        const uint32_t khBase = khB + ((((tt & 1)*64)*KH_STRIDE) << 2);

        uint32_t ph[2][4][4];
        #pragma unroll
        for (int half = 0; half < 2; half++) {
            float s[8][4];
            #pragma unroll
            for (int n=0;n<8;n++)
                #pragma unroll
                for (int i=0;i<4;i++) s[n][i] = 0.f;

            #pragma unroll
            for (int kc = 0; kc < 2; kc++) {
                const int kb = half*16 + kc*8;
                uint32_t bf[4][4];
                #pragma unroll
                for (int nj = 0; nj < 4; nj++)
                    ldsm4(bf[nj], khBase + (((nj*16 + lb)*KH_STRIDE + kb + sb*4) << 2));
                #pragma unroll
                for (int n = 0; n < 8; n++)
                    mma_f16(s[n], qh[half][kc],
                            bf[n>>1][(n&1)*2], bf[n>>1][(n&1)*2+1]);
            }
            #pragma unroll
            for (int n = 0; n < 8; n++) {
                float p0 = ex2f(s[n][0]);
                float p1 = ex2f(s[n][1]);
                float p2 = ex2f(s[n][2]);
                float p3 = ex2f(s[n][3]);
                lsum[half][0] += p0 + p1;
                lsum[half][1] += p2 + p3;
                int ks = n >> 1, hi = (n & 1) * 2;
                ph[half][ks][hi    ] = packh2(p0, p1);
                ph[half][ks][hi + 1] = packh2(p2, p3);
            }
        }

        #pragma unroll
        for (int ks = 0; ks < 4; ks++) {
            uint32_t vf[2][4];
            #pragma unroll
            for (int nj = 0; nj < 2; nj++)
                ldsm4(vf[nj], vtB + (((nj*16 + lb)*VT_STRIDE + ks*8 + sb*4) << 2));
            #pragma unroll
            for (int n = 0; n < 4; n++) {
                uint32_t b0 = vf[n>>1][(n&1)*2], b1 = vf[n>>1][(n&1)*2+1];
                mma_f16(o[0][n], ph[0][ks], b0, b1);
                mma_f16(o[1][n], ph[1][ks], b0, b1);
            }
        }
    }

    #pragma unroll
    for (int hf = 0; hf < 2; hf++) {
        #pragma unroll
        for (int r2 = 0; r2 < 2; r2++) {
            float v = lsum[hf][r2];
            v += __shfl_xor_sync(0xffffffffu, v, 1);
            v += __shfl_xor_sync(0xffffffffu, v, 2);
            lsum[hf][r2] = v;
        }
    }
    const float i1A = 1.f / lsum[0][0];
    const float i1B = 1.f / lsum[0][1];
    const float s2A = lam / lsum[1][0];
    const float s2B = lam / lsum[1][1];

    uint32_t* outA = (uint32_t*)(O + ((size_t)(b*NN + qw + gr    ))*DIM + h*HD);
    uint32_t* outB = (uint32_t*)(O + ((size_t)(b*NN + qw + gr + 8))*DIM + h*HD);
    #pragma unroll
    for (int n = 0; n < 4; n++) {
        outA[(n*8 + 2*gc) >> 1] = packh2(o[0][n][0]*i1A - o[1][n][0]*s2A,
                                         o[0][n][1]*i1A - o[1][n][1]*s2A);
        outB[(n*8 + 2*gc) >> 1] = packh2(o[0][n][2]*i1B - o[1][n][2]*s2B,
                                         o[0][n][3]*i1B - o[1][n][3]*s2B);
    }
}

// ---------------- launch ----------------------------------------------------
static void* symp(const void* sym) {
    void* p = nullptr;
    cudaGetSymbolAddress(&p, sym);
    return p;
}

extern "C" void kernel_launch(void* const* d_in, const int* in_sizes, int n_in,
                              void* d_out, int out_size)
{
    const float* drift = (const float*)d_in[0];
    const float* ocean = (const float*)d_in[1];
    const float* Wq    = (const float*)d_in[2];
    const float* Wk    = (const float*)d_in[3];
    const float* Wv    = (const float*)d_in[4];
    const float* Wo    = (const float*)d_in[5];
    const float* lq1   = (const float*)d_in[6];
    const float* lk1   = (const float*)d_in[7];
    const float* lq2   = (const float*)d_in[8];
    const float* lk2   = (const float*)d_in[9];
    const float* gamma = (const float*)d_in[10];
    const float* beta  = (const float*)d_in[11];
    const float* fc1w  = (const float*)d_in[12];
    const float* fc1b  = (const float*)d_in[13];
    const float* fc2w  = (const float*)d_in[14];
    const float* fc2b  = (const float*)d_in[15];
    float* out = (float*)d_out;

    __half* hw   = (__half*)symp(g_hw);
    __half* hx   = (__half*)symp(g_hx);
    __half* hQ   = (__half*)symp(g_hQ);
    __half* hKV  = (__half*)symp(g_hKV);
    __half* hatt = (__half*)symp(g_hatt);
    __half* hy   = (__half*)symp(g_hy);
    __half* hh   = (__half*)symp(g_hh);

    cudaFuncSetAttribute((const void*)gemm_qkv,      cudaFuncAttributeMaxDynamicSharedMemorySize, GEMM_SMEM(64));
    cudaFuncSetAttribute((const void*)gemm_h<1,64>,  cudaFuncAttributeMaxDynamicSharedMemorySize, GEMM_SMEM(64));
    cudaFuncSetAttribute((const void*)gemm_h<2,128>, cudaFuncAttributeMaxDynamicSharedMemorySize, GEMM_SMEM(128));
    cudaFuncSetAttribute((const void*)gemm_h<3,64>,  cudaFuncAttributeMaxDynamicSharedMemorySize, GEMM_SMEM(64));

    // 0) fused: LN1 + weight/ocean conversion (+ ocean passthrough)
    ln_cvt_kernel<<<512 + (HW_TOTAL/4 + 255)/256, 256>>>(
        drift, hx, gamma, beta,
        ocean, Wq, Wk, Wv, Wo, fc1w, fc2w, hw, out + (size_t)ROWS*DIM);
    // 1) fused Q + KV projections (one launch)
    gemm_qkv<<<dim3(20, ROWS/128), 256, GEMM_SMEM(64)>>>(hx, hw+WQ_OFF, hQ,
                                                         hw+OC_OFF, hw+WK_OFF, hKV);
    // 2) differential attention (cp.async double-buffered K)
    attn_tc<<<dim3(NN/128, HH, BB), 256>>>(hQ, hKV, lq1, lk1, lq2, lk2, hatt);
    // 3) drift2 = drift + att @ Wo^T -> out (fp32)
    gemm_h<1,64><<<dim3(256/64, ROWS/128), 256, GEMM_SMEM(64)>>>(hatt, hw+WO_OFF, nullptr, drift, out, 256, 256, 1.0f);
    // 4) y = LN(drift2) -> half
    ln_half<<<ROWS/8, 256>>>(out, hy, gamma, beta);
    // 5) h = gelu(y @ fc1^T + b1)
    gemm_h<2,128><<<dim3(1024/128, ROWS/128), 256, GEMM_SMEM(128)>>>(hy, hw+F1_OFF, fc1b, nullptr, hh, 1024, 256, 1.0f);
    // 6) drift_out = drift2 + h @ fc2^T + b2 (in-place on out)
    gemm_h<3,64><<<dim3(256/64, ROWS/128), 256, GEMM_SMEM(64)>>>(hh, hw+F2_OFF, fc2b, out, out, 256, 1024, 1.0f);
}